// round 3
// baseline (speedup 1.0000x reference)
#include <cuda_runtime.h>
#include <cuda_bf16.h>
#include <cstdint>

// Problem constants (fixed by dataset); runtime sizes still read from in_sizes.
#define MAXN 50016          // >= N=50000, padded
#define BT   64             // batch size (hardcoded in reference via repeat(64,1,1))

// Scratch: __device__ globals (no allocation allowed).
// Each [MAXN][64] fp32 tile = 12.8 MB. Total ~38.6 MB, all L2-resident at runtime.
__device__ float4 g_xT [MAXN * (BT / 4)];   // x transposed: [N][64], float4 view
__device__ float4 g_mr [MAXN * (BT / 4)];   // reaction messages  [N][64]
__device__ float4 g_md [MAXN * (BT / 4)];   // diffusion messages [N][64]
__device__ float  g_cr [MAXN];              // reaction col sums
__device__ float  g_cd [MAXN];              // diffusion col sums

// 16-byte vector reduction to global (sm_90+). No return value -> RED in SASS.
__device__ __forceinline__ void red_add_v4(float* p, float4 v) {
    asm volatile("red.global.add.v4.f32 [%0], {%1, %2, %3, %4};"
                 :: "l"(p), "f"(v.x), "f"(v.y), "f"(v.z), "f"(v.w)
                 : "memory");
}

// ---------------------------------------------------------------------------
// Kernel 1: transpose input [B,N] -> xT [N,B]  (tiled via smem, coalesced both ways)
// ---------------------------------------------------------------------------
__global__ void k_transpose_in(const float* __restrict__ in,
                               float* __restrict__ xT, int n) {
    __shared__ float tile[32][BT + 1];
    const int v0 = blockIdx.x * 32;
    const int t  = threadIdx.x;           // 256 threads

    // Read: consecutive threads -> consecutive v (coalesced rows of input)
    #pragma unroll
    for (int k = t; k < 32 * BT; k += 256) {
        int b  = k >> 5;                  // 0..63
        int vl = k & 31;
        int v  = v0 + vl;
        tile[vl][b] = (v < n) ? in[(size_t)b * n + v] : 0.0f;
    }
    __syncthreads();
    // Write: consecutive threads -> consecutive b (coalesced rows of xT)
    #pragma unroll
    for (int k = t; k < 32 * BT; k += 256) {
        int vl = k >> 6;                  // 0..31
        int b  = k & 63;
        int v  = v0 + vl;
        if (v < n) xT[(size_t)v * BT + b] = tile[vl][b];
    }
}

// ---------------------------------------------------------------------------
// Kernel 2: COO edge pass. One warp per 32-edge chunk.
//   reaction : msg_r[i] += wr * xT[j] ; col_r[j] += wr
//   diffusion: msg_d[j] += wd * xT[i] ; col_d[i] += wd
// Half-warp (lanes 0-15) handles reaction, lanes 16-31 diffusion; each lane one float4.
// ---------------------------------------------------------------------------
__global__ void k_edge_pass(const int*   __restrict__ ei,
                            const int*   __restrict__ ej,
                            const float* __restrict__ wr,
                            const float* __restrict__ wd,
                            const float4* __restrict__ xT,
                            float4* __restrict__ mr,
                            float4* __restrict__ md,
                            float* __restrict__ cr,
                            float* __restrict__ cd,
                            int e) {
    const int gw   = (blockIdx.x * blockDim.x + threadIdx.x) >> 5;
    const int lane = threadIdx.x & 31;
    const int base = gw * 32;
    if (base >= e) return;
    const int cnt = min(32, e - base);

    int   i_l = 0, j_l = 0;
    float wr_l = 0.f, wd_l = 0.f;
    if (lane < cnt) {
        i_l  = __ldg(ei + base + lane);
        j_l  = __ldg(ej + base + lane);
        wr_l = __ldg(wr + base + lane);
        wd_l = __ldg(wd + base + lane);
        // column sums (scalar RED, spread addresses)
        atomicAdd(cr + j_l, wr_l);
        atomicAdd(cd + i_l, wd_l);
    }

    const int half = lane >> 4;           // 0 = reaction, 1 = diffusion
    const int q    = lane & 15;           // float4 slot within 64-float row
    float4* const tgt = half ? md : mr;

    for (int s = 0; s < cnt; s++) {
        const int   i  = __shfl_sync(0xffffffffu, i_l,  s);
        const int   j  = __shfl_sync(0xffffffffu, j_l,  s);
        const float wrv = __shfl_sync(0xffffffffu, wr_l, s);
        const float wdv = __shfl_sync(0xffffffffu, wd_l, s);

        const int   src = half ? i : j;   // gather node
        const int   dst = half ? j : i;   // scatter node
        const float w   = half ? wdv : wrv;

        float4 xv = __ldg(&xT[src * (BT / 4) + q]);     // 256B L2 gather per half-warp
        float4 r  = make_float4(w * xv.x, w * xv.y, w * xv.z, w * xv.w);
        red_add_v4((float*)&tgt[dst * (BT / 4) + q], r); // 256B L2 reduction per half-warp
    }
}

// ---------------------------------------------------------------------------
// Kernel 3: combine + transpose out.
//   out[b,v] = tanh(cr[v]*x - mr[v,b] + br[v]) + (cd[v]*x - md[v,b] + bd[v]) + x
// ---------------------------------------------------------------------------
__global__ void k_combine(const float* __restrict__ xT,
                          const float* __restrict__ mr,
                          const float* __restrict__ md,
                          const float* __restrict__ cr,
                          const float* __restrict__ cd,
                          const float* __restrict__ br,
                          const float* __restrict__ bd,
                          float* __restrict__ out, int n) {
    __shared__ float tile[32][BT + 1];
    const int v0 = blockIdx.x * 32;
    const int t  = threadIdx.x;

    #pragma unroll
    for (int k = t; k < 32 * BT; k += 256) {
        int vl = k >> 6;
        int b  = k & 63;
        int v  = v0 + vl;
        if (v < n) {
            size_t idx = (size_t)v * BT + b;
            float x  = xT[idx];
            float rr = cr[v] * x - mr[idx] + br[v];
            float dd = cd[v] * x - md[idx] + bd[v];
            tile[vl][b] = tanhf(rr) + dd + x;
        }
    }
    __syncthreads();
    #pragma unroll
    for (int k = t; k < 32 * BT; k += 256) {
        int b  = k >> 5;
        int vl = k & 31;
        int v  = v0 + vl;
        if (v < n) out[(size_t)b * n + v] = tile[vl][b];
    }
}

// ---------------------------------------------------------------------------
// Launch: metadata order is t, input, edge_i, edge_j, weight_react, weight_diff,
//         bias_reaction, bias_diffusion. Output fp32 [B, N].
// ---------------------------------------------------------------------------
extern "C" void kernel_launch(void* const* d_in, const int* in_sizes, int n_in,
                              void* d_out, int out_size) {
    const float* input = (const float*)d_in[1];
    const int*   ei    = (const int*)  d_in[2];
    const int*   ej    = (const int*)  d_in[3];
    const float* wr    = (const float*)d_in[4];
    const float* wd    = (const float*)d_in[5];
    const float* br    = (const float*)d_in[6];
    const float* bd    = (const float*)d_in[7];
    float*       out   = (float*)d_out;

    const int n = in_sizes[6];   // bias_reaction has N elements
    const int e = in_sizes[2];   // edge count

    void *pxT, *pmr, *pmd, *pcr, *pcd;
    cudaGetSymbolAddress(&pxT, g_xT);
    cudaGetSymbolAddress(&pmr, g_mr);
    cudaGetSymbolAddress(&pmd, g_md);
    cudaGetSymbolAddress(&pcr, g_cr);
    cudaGetSymbolAddress(&pcd, g_cd);

    // Zero accumulators (graph-capturable memset nodes).
    cudaMemsetAsync(pmr, 0, (size_t)n * BT * sizeof(float));
    cudaMemsetAsync(pmd, 0, (size_t)n * BT * sizeof(float));
    cudaMemsetAsync(pcr, 0, (size_t)n * sizeof(float));
    cudaMemsetAsync(pcd, 0, (size_t)n * sizeof(float));

    const int nvblocks = (n + 31) / 32;
    k_transpose_in<<<nvblocks, 256>>>(input, (float*)pxT, n);

    const int nchunks = (e + 31) / 32;              // one warp per 32-edge chunk
    const int eblocks = (nchunks + 7) / 8;          // 8 warps per block
    k_edge_pass<<<eblocks, 256>>>(ei, ej, wr, wd,
                                  (const float4*)pxT,
                                  (float4*)pmr, (float4*)pmd,
                                  (float*)pcr, (float*)pcd, e);

    k_combine<<<nvblocks, 256>>>((const float*)pxT,
                                 (const float*)pmr, (const float*)pmd,
                                 (const float*)pcr, (const float*)pcd,
                                 br, bd, out, n);
}